// round 4
// baseline (speedup 1.0000x reference)
#include <cuda_runtime.h>

// Problem constants
#define B_SZ 4096
#define T_SZ 200
#define D_SZ 64
#define P_SZ 2
#define TM1 (T_SZ - 1)   // 199
#define COV_ROW (D_SZ + 1) // 65 floats

#define GRID_N 4096      // one block per batch element
#define BLOCK_N 256

// Per-block partials (overwritten every launch -> no init kernel needed)
__device__ float g_part_step[GRID_N];
__device__ float g_part_drift[GRID_N];
__device__ float g_part_gdiff[GRID_N];
__device__ unsigned int g_ticket = 0;   // wraps back to 0 on the last block

// Reduce one float across the block; result valid on thread 0.
__device__ __forceinline__ float block_reduce(float v, float* shmem) {
    #pragma unroll
    for (int off = 16; off > 0; off >>= 1)
        v += __shfl_down_sync(0xFFFFFFFFu, v, off);
    int lane = threadIdx.x & 31;
    int wid  = threadIdx.x >> 5;
    if (lane == 0) shmem[wid] = v;
    __syncthreads();
    int nwarps = BLOCK_N >> 5;
    if (wid == 0) {
        float s = (lane < nwarps) ? shmem[lane] : 0.0f;
        #pragma unroll
        for (int off = 16; off > 0; off >>= 1)
            s += __shfl_down_sync(0xFFFFFFFFu, s, off);
        return s;
    }
    return 0.0f;
}

__global__ void __launch_bounds__(BLOCK_N)
fused_kernel(const float* __restrict__ pred_params,
             const float* __restrict__ step_preds,
             const float* __restrict__ cov,
             const float* __restrict__ theta,
             const int*   __restrict__ lengths,
             float*       __restrict__ out) {
    __shared__ float shmem[32];

    // ---- Phase 1: step-ahead term. Block b owns batch b. ----
    // 16 groups of 16 lanes; group g handles rows t = g, g+16, ...
    // Uniform loop bound per block: zero divergence, zero dead iterations.
    {
        const int b    = blockIdx.x;
        const int g    = threadIdx.x >> 4;
        const int lane = threadIdx.x & 15;
        const int len  = lengths[b];
        const int nrow = len - 1;                  // rows 0..nrow-1 are live

        float local = 0.0f;
        if (nrow > 0) {
            const float w = 1.0f / ((float)nrow * (float)D_SZ);
            const float* __restrict__ pbase =
                step_preds + (size_t)b * TM1 * D_SZ + (lane << 2);
            const float* __restrict__ cbase =
                cov + (size_t)b * T_SZ * COV_ROW + COV_ROW + 1 + (lane << 2);

            int t = g;
            // Unrolled by 2 rows: ~10 loads in flight per thread.
            for (; t + 16 < nrow; t += 32) {
                const float4 p0 = *reinterpret_cast<const float4*>(pbase + (size_t)t * D_SZ);
                const float4 p1 = *reinterpret_cast<const float4*>(pbase + (size_t)(t + 16) * D_SZ);
                const float* c0 = cbase + (size_t)t * COV_ROW;
                const float* c1 = cbase + (size_t)(t + 16) * COV_ROW;
                float a0 = c0[0] - p0.x, a1 = c0[1] - p0.y;
                float a2 = c0[2] - p0.z, a3 = c0[3] - p0.w;
                float b0 = c1[0] - p1.x, b1 = c1[1] - p1.y;
                float b2 = c1[2] - p1.z, b3 = c1[3] - p1.w;
                local += a0*a0 + a1*a1 + a2*a2 + a3*a3
                       + b0*b0 + b1*b1 + b2*b2 + b3*b3;
            }
            if (t < nrow) {
                const float4 p0 = *reinterpret_cast<const float4*>(pbase + (size_t)t * D_SZ);
                const float* c0 = cbase + (size_t)t * COV_ROW;
                float a0 = c0[0] - p0.x, a1 = c0[1] - p0.y;
                float a2 = c0[2] - p0.z, a3 = c0[3] - p0.w;
                local += a0*a0 + a1*a1 + a2*a2 + a3*a3;
            }
            local *= w;
        }
        float s = block_reduce(local, shmem);
        if (threadIdx.x == 0) g_part_step[blockIdx.x] = s;
        __syncthreads();  // shmem reuse
    }

    // ---- Phase 2: drift + global-diff over pred_params [B,T,2] ----
    // 4096*256 threads >= 819200 elements: exactly one float2 per thread.
    {
        const float inv_th0 = 1.0f / theta[0];
        const float inv_th1 = 1.0f / theta[1];
        const int n = B_SZ * T_SZ;
        const int i = blockIdx.x * BLOCK_N + threadIdx.x;

        float drift = 0.0f;
        float gdiff = 0.0f;
        if (i < n) {
            int t = i % T_SZ;
            float2 x = reinterpret_cast<const float2*>(pred_params)[i];
            float e0 = x.x * inv_th0 - 1.0f;
            float e1 = x.y * inv_th1 - 1.0f;
            gdiff = e0 * e0 + e1 * e1;
            if (t < T_SZ - 1) {
                float2 y = reinterpret_cast<const float2*>(pred_params)[i + 1];
                float d0 = x.x - y.x;
                float d1 = x.y - y.y;
                drift = d0 * d0 + d1 * d1;
            }
        }
        float sd = block_reduce(drift, shmem);
        if (threadIdx.x == 0) g_part_drift[blockIdx.x] = sd;
        __syncthreads();
        float sg = block_reduce(gdiff, shmem);
        if (threadIdx.x == 0) g_part_gdiff[blockIdx.x] = sg;
    }

    // ---- Phase 3: last block finalizes ----
    __shared__ bool is_last;
    __threadfence();
    if (threadIdx.x == 0) {
        unsigned int t = atomicInc(&g_ticket, GRID_N - 1);
        is_last = (t == GRID_N - 1);   // wraps to 0 for next replay
    }
    __syncthreads();
    if (!is_last) return;

    double a0 = 0.0, a1 = 0.0, a2 = 0.0;
    for (int i = threadIdx.x; i < GRID_N; i += BLOCK_N) {
        a0 += (double)g_part_step[i];
        a1 += (double)g_part_drift[i];
        a2 += (double)g_part_gdiff[i];
    }
    __shared__ double dsh[3][32];
    #pragma unroll
    for (int off = 16; off > 0; off >>= 1) {
        a0 += __shfl_down_sync(0xFFFFFFFFu, a0, off);
        a1 += __shfl_down_sync(0xFFFFFFFFu, a1, off);
        a2 += __shfl_down_sync(0xFFFFFFFFu, a2, off);
    }
    int lane = threadIdx.x & 31;
    int wid  = threadIdx.x >> 5;
    if (lane == 0) { dsh[0][wid] = a0; dsh[1][wid] = a1; dsh[2][wid] = a2; }
    __syncthreads();
    if (wid == 0) {
        int nwarps = BLOCK_N >> 5;
        a0 = (lane < nwarps) ? dsh[0][lane] : 0.0;
        a1 = (lane < nwarps) ? dsh[1][lane] : 0.0;
        a2 = (lane < nwarps) ? dsh[2][lane] : 0.0;
        #pragma unroll
        for (int off = 16; off > 0; off >>= 1) {
            a0 += __shfl_down_sync(0xFFFFFFFFu, a0, off);
            a1 += __shfl_down_sync(0xFFFFFFFFu, a1, off);
            a2 += __shfl_down_sync(0xFFFFFFFFu, a2, off);
        }
        if (lane == 0) {
            double step  = a0 / (double)B_SZ;
            double drift = a1 / ((double)B_SZ * (double)TM1 * (double)P_SZ);
            double gdiff = a2 / ((double)B_SZ * (double)T_SZ * (double)P_SZ);
            out[0] = (float)(step + 0.1 * drift + 0.01 * gdiff);
        }
    }
}

extern "C" void kernel_launch(void* const* d_in, const int* in_sizes, int n_in,
                              void* d_out, int out_size) {
    const float* global_theta = (const float*)d_in[0];
    const float* pred_params  = (const float*)d_in[1];
    // d_in[2] = hidden_states: UNUSED by the reference
    const float* step_preds   = (const float*)d_in[3];
    const float* cov_trajs    = (const float*)d_in[4];
    const int*   lengths      = (const int*)d_in[5];
    float* out = (float*)d_out;

    fused_kernel<<<GRID_N, BLOCK_N>>>(pred_params, step_preds, cov_trajs,
                                      global_theta, lengths, out);
}

// round 6
// speedup vs baseline: 1.0774x; 1.0774x over previous
#include <cuda_runtime.h>

// Problem constants
#define B_SZ 4096
#define T_SZ 200
#define D_SZ 64
#define P_SZ 2
#define TM1 (T_SZ - 1)     // 199
#define COV_ROW (D_SZ + 1) // 65

#define GRID_N 2048
#define BLOCK_N 256

// Per-block partials: overwritten every launch, no init needed.
__device__ float g_part_step[GRID_N];
__device__ float g_part_drift[GRID_N];
__device__ float g_part_gdiff[GRID_N];

// Reduce one float across the block; result valid on thread 0.
__device__ __forceinline__ float block_reduce(float v, float* shmem) {
    #pragma unroll
    for (int off = 16; off > 0; off >>= 1)
        v += __shfl_down_sync(0xFFFFFFFFu, v, off);
    int lane = threadIdx.x & 31;
    int wid  = threadIdx.x >> 5;
    if (lane == 0) shmem[wid] = v;
    __syncthreads();
    if (wid == 0) {
        float s = (lane < (BLOCK_N >> 5)) ? shmem[lane] : 0.0f;
        #pragma unroll
        for (int off = 16; off > 0; off >>= 1)
            s += __shfl_down_sync(0xFFFFFFFFu, s, off);
        return s;
    }
    return 0.0f;
}

// Process one (b,t) row with 16 lanes; returns weighted partial (0 if dead).
__device__ __forceinline__ float row_term(const float* __restrict__ pred,
                                          const float* __restrict__ cov,
                                          const int*   __restrict__ lengths,
                                          int row, int lane) {
    int b = row / TM1;
    int t = row - b * TM1;
    int len = lengths[b];
    bool live = (t < len - 1);
    float acc = 0.0f;
    if (live) {
        const float4 p = *reinterpret_cast<const float4*>(
            pred + (size_t)row * D_SZ + (lane << 2));
        const float* c = cov + (size_t)b * T_SZ * COV_ROW
                             + (size_t)(t + 1) * COV_ROW + 1 + (lane << 2);
        float d0 = c[0] - p.x;
        float d1 = c[1] - p.y;
        float d2 = c[2] - p.z;
        float d3 = c[3] - p.w;
        float w = 1.0f / ((float)(len - 1) * (float)D_SZ);
        acc = w * (d0 * d0 + d1 * d1 + d2 * d2 + d3 * d3);
    }
    return acc;
}

__global__ void __launch_bounds__(BLOCK_N)
main_kernel(const float* __restrict__ pred_params,
            const float* __restrict__ step_preds,
            const float* __restrict__ cov,
            const float* __restrict__ theta,
            const int*   __restrict__ lengths) {
    __shared__ float shmem[32];

    // ---- Phase 1: step-ahead term, flat row mapping, 2 rows in flight ----
    {
        const int groups_per_block = BLOCK_N >> 4;
        const int gid    = blockIdx.x * groups_per_block + (threadIdx.x >> 4);
        const int lane   = threadIdx.x & 15;
        const int n_grps = GRID_N * groups_per_block;
        const int n_rows = B_SZ * TM1;

        float local = 0.0f;
        int row = gid;
        for (; row + n_grps < n_rows; row += 2 * n_grps) {
            local += row_term(step_preds, cov, lengths, row, lane);
            local += row_term(step_preds, cov, lengths, row + n_grps, lane);
        }
        if (row < n_rows)
            local += row_term(step_preds, cov, lengths, row, lane);

        float s = block_reduce(local, shmem);
        if (threadIdx.x == 0) g_part_step[blockIdx.x] = s;
        __syncthreads();  // shmem reuse
    }

    // ---- Phase 2: drift + global-diff over pred_params [B,T,2] ----
    // n = B*T = 819200 float2 elements; grid-stride (524288 threads -> 1-2 each).
    {
        const float inv_th0 = 1.0f / theta[0];
        const float inv_th1 = 1.0f / theta[1];
        const int n = B_SZ * T_SZ;
        const int stride = GRID_N * BLOCK_N;

        float drift = 0.0f;
        float gdiff = 0.0f;
        for (int i = blockIdx.x * BLOCK_N + threadIdx.x; i < n; i += stride) {
            int t = i % T_SZ;
            float2 x = reinterpret_cast<const float2*>(pred_params)[i];
            float e0 = x.x * inv_th0 - 1.0f;
            float e1 = x.y * inv_th1 - 1.0f;
            gdiff += e0 * e0 + e1 * e1;
            if (t < T_SZ - 1) {
                float2 y = reinterpret_cast<const float2*>(pred_params)[i + 1];
                float d0 = x.x - y.x;
                float d1 = x.y - y.y;
                drift += d0 * d0 + d1 * d1;
            }
        }
        float sd = block_reduce(drift, shmem);
        if (threadIdx.x == 0) g_part_drift[blockIdx.x] = sd;
        __syncthreads();
        float sg = block_reduce(gdiff, shmem);
        if (threadIdx.x == 0) g_part_gdiff[blockIdx.x] = sg;
    }
}

__global__ void __launch_bounds__(BLOCK_N)
finalize_kernel(float* __restrict__ out) {
    double a0 = 0.0, a1 = 0.0, a2 = 0.0;
    for (int i = threadIdx.x; i < GRID_N; i += BLOCK_N) {
        a0 += (double)g_part_step[i];
        a1 += (double)g_part_drift[i];
        a2 += (double)g_part_gdiff[i];
    }
    __shared__ double dsh[3][32];
    #pragma unroll
    for (int off = 16; off > 0; off >>= 1) {
        a0 += __shfl_down_sync(0xFFFFFFFFu, a0, off);
        a1 += __shfl_down_sync(0xFFFFFFFFu, a1, off);
        a2 += __shfl_down_sync(0xFFFFFFFFu, a2, off);
    }
    int lane = threadIdx.x & 31;
    int wid  = threadIdx.x >> 5;
    if (lane == 0) { dsh[0][wid] = a0; dsh[1][wid] = a1; dsh[2][wid] = a2; }
    __syncthreads();
    if (wid == 0) {
        a0 = (lane < (BLOCK_N >> 5)) ? dsh[0][lane] : 0.0;
        a1 = (lane < (BLOCK_N >> 5)) ? dsh[1][lane] : 0.0;
        a2 = (lane < (BLOCK_N >> 5)) ? dsh[2][lane] : 0.0;
        #pragma unroll
        for (int off = 16; off > 0; off >>= 1) {
            a0 += __shfl_down_sync(0xFFFFFFFFu, a0, off);
            a1 += __shfl_down_sync(0xFFFFFFFFu, a1, off);
            a2 += __shfl_down_sync(0xFFFFFFFFu, a2, off);
        }
        if (lane == 0) {
            double step  = a0 / (double)B_SZ;
            double drift = a1 / ((double)B_SZ * (double)TM1 * (double)P_SZ);
            double gdiff = a2 / ((double)B_SZ * (double)T_SZ * (double)P_SZ);
            out[0] = (float)(step + 0.1 * drift + 0.01 * gdiff);
        }
    }
}

extern "C" void kernel_launch(void* const* d_in, const int* in_sizes, int n_in,
                              void* d_out, int out_size) {
    const float* global_theta = (const float*)d_in[0];
    const float* pred_params  = (const float*)d_in[1];
    // d_in[2] = hidden_states: UNUSED by the reference
    const float* step_preds   = (const float*)d_in[3];
    const float* cov_trajs    = (const float*)d_in[4];
    const int*   lengths      = (const int*)d_in[5];
    float* out = (float*)d_out;

    main_kernel<<<GRID_N, BLOCK_N>>>(pred_params, step_preds, cov_trajs,
                                     global_theta, lengths);
    finalize_kernel<<<1, BLOCK_N>>>(out);
}

// round 8
// speedup vs baseline: 1.2339x; 1.1453x over previous
#include <cuda_runtime.h>

// Problem constants
#define B_SZ 4096
#define T_SZ 200
#define D_SZ 64
#define P_SZ 2
#define TM1 (T_SZ - 1)     // 199
#define COV_ROW (D_SZ + 1) // 65

#define GRID_N 2048
#define BLOCK_N 256

// Global accumulators. Start at 0 (static init); the finalizing block resets
// them to 0 after use, so every graph replay sees zeros. Ticket wraps to 0.
__device__ double g_acc[3] = {0.0, 0.0, 0.0};
__device__ unsigned int g_ticket = 0;

// Reduce one float across the block; result valid on thread 0.
__device__ __forceinline__ float block_reduce(float v, float* shmem) {
    #pragma unroll
    for (int off = 16; off > 0; off >>= 1)
        v += __shfl_down_sync(0xFFFFFFFFu, v, off);
    int lane = threadIdx.x & 31;
    int wid  = threadIdx.x >> 5;
    if (lane == 0) shmem[wid] = v;
    __syncthreads();
    if (wid == 0) {
        float s = (lane < (BLOCK_N >> 5)) ? shmem[lane] : 0.0f;
        #pragma unroll
        for (int off = 16; off > 0; off >>= 1)
            s += __shfl_down_sync(0xFFFFFFFFu, s, off);
        return s;
    }
    return 0.0f;
}

// One (b,t) row with 16 lanes; returns weighted partial (0 if dead).
__device__ __forceinline__ float row_term(const float* __restrict__ pred,
                                          const float* __restrict__ cov,
                                          const int*   __restrict__ lengths,
                                          int row, int lane) {
    int b = row / TM1;
    int t = row - b * TM1;
    int len = lengths[b];
    float acc = 0.0f;
    if (t < len - 1) {
        const float4 p = __ldcs(reinterpret_cast<const float4*>(
            pred + (size_t)row * D_SZ + (lane << 2)));
        const float* c = cov + (size_t)b * T_SZ * COV_ROW
                             + (size_t)(t + 1) * COV_ROW + 1 + (lane << 2);
        float d0 = __ldcs(c + 0) - p.x;
        float d1 = __ldcs(c + 1) - p.y;
        float d2 = __ldcs(c + 2) - p.z;
        float d3 = __ldcs(c + 3) - p.w;
        float w = 1.0f / ((float)(len - 1) * (float)D_SZ);
        acc = w * (d0 * d0 + d1 * d1 + d2 * d2 + d3 * d3);
    }
    return acc;
}

__global__ void __launch_bounds__(BLOCK_N)
main_kernel(const float* __restrict__ pred_params,
            const float* __restrict__ step_preds,
            const float* __restrict__ cov,
            const float* __restrict__ theta,
            const int*   __restrict__ lengths,
            float*       __restrict__ out) {
    __shared__ float shmem[32];

    float block_step, block_drift, block_gdiff;

    // ---- Phase 1: step-ahead term, flat row mapping, 2 rows in flight ----
    {
        const int groups_per_block = BLOCK_N >> 4;
        const int gid    = blockIdx.x * groups_per_block + (threadIdx.x >> 4);
        const int lane   = threadIdx.x & 15;
        const int n_grps = GRID_N * groups_per_block;
        const int n_rows = B_SZ * TM1;

        float local = 0.0f;
        int row = gid;
        for (; row + n_grps < n_rows; row += 2 * n_grps) {
            local += row_term(step_preds, cov, lengths, row, lane);
            local += row_term(step_preds, cov, lengths, row + n_grps, lane);
        }
        if (row < n_rows)
            local += row_term(step_preds, cov, lengths, row, lane);

        block_step = block_reduce(local, shmem);
        __syncthreads();  // shmem reuse
    }

    // ---- Phase 2: drift + global-diff over pred_params [B,T,2] ----
    {
        const float inv_th0 = 1.0f / theta[0];
        const float inv_th1 = 1.0f / theta[1];
        const int n = B_SZ * T_SZ;   // 819200 float2 elements
        const int stride = GRID_N * BLOCK_N;

        float drift = 0.0f;
        float gdiff = 0.0f;
        for (int i = blockIdx.x * BLOCK_N + threadIdx.x; i < n; i += stride) {
            int t = i % T_SZ;
            float2 x = reinterpret_cast<const float2*>(pred_params)[i];
            float e0 = x.x * inv_th0 - 1.0f;
            float e1 = x.y * inv_th1 - 1.0f;
            gdiff += e0 * e0 + e1 * e1;
            if (t < T_SZ - 1) {
                float2 y = reinterpret_cast<const float2*>(pred_params)[i + 1];
                float d0 = x.x - y.x;
                float d1 = x.y - y.y;
                drift += d0 * d0 + d1 * d1;
            }
        }
        block_drift = block_reduce(drift, shmem);
        __syncthreads();
        block_gdiff = block_reduce(gdiff, shmem);
    }

    // ---- Phase 3: thread-0-only commit + ticket; last block finalizes ----
    __shared__ bool is_last;
    if (threadIdx.x == 0) {
        atomicAdd(&g_acc[0], (double)block_step);
        atomicAdd(&g_acc[1], (double)block_drift);
        atomicAdd(&g_acc[2], (double)block_gdiff);
        __threadfence();   // order my adds before my ticket (1 thread only)
        unsigned int t = atomicInc(&g_ticket, GRID_N - 1);  // wraps to 0
        is_last = (t == GRID_N - 1);
    }
    __syncthreads();
    if (!is_last) return;

    if (threadIdx.x == 0) {
        __threadfence();   // acquire: see all committed atomics
        double step  = g_acc[0] / (double)B_SZ;
        double drift = g_acc[1] / ((double)B_SZ * (double)TM1 * (double)P_SZ);
        double gdiff = g_acc[2] / ((double)B_SZ * (double)T_SZ * (double)P_SZ);
        out[0] = (float)(step + 0.1 * drift + 0.01 * gdiff);
        // Reset for the next graph replay.
        g_acc[0] = 0.0; g_acc[1] = 0.0; g_acc[2] = 0.0;
        __threadfence();
    }
}

extern "C" void kernel_launch(void* const* d_in, const int* in_sizes, int n_in,
                              void* d_out, int out_size) {
    const float* global_theta = (const float*)d_in[0];
    const float* pred_params  = (const float*)d_in[1];
    // d_in[2] = hidden_states: UNUSED by the reference
    const float* step_preds   = (const float*)d_in[3];
    const float* cov_trajs    = (const float*)d_in[4];
    const int*   lengths      = (const int*)d_in[5];
    float* out = (float*)d_out;

    main_kernel<<<GRID_N, BLOCK_N>>>(pred_params, step_preds, cov_trajs,
                                     global_theta, lengths, out);
}

// round 9
// speedup vs baseline: 1.2417x; 1.0063x over previous
#include <cuda_runtime.h>

// Problem constants
#define B_SZ 4096
#define T_SZ 200
#define D_SZ 64
#define P_SZ 2
#define TM1 (T_SZ - 1)     // 199
#define COV_ROW (D_SZ + 1) // 65

#define GRID_N 2048
#define BLOCK_N 256

// Global accumulators + work queue. Static-init to 0; the finalizing block
// resets everything for the next graph replay.
__device__ double g_acc[3] = {0.0, 0.0, 0.0};
__device__ unsigned int g_ticket = 0;
__device__ unsigned int g_batch_ctr = 0;

// Reduce one float across the block; result valid on thread 0.
__device__ __forceinline__ float block_reduce(float v, float* shmem) {
    #pragma unroll
    for (int off = 16; off > 0; off >>= 1)
        v += __shfl_down_sync(0xFFFFFFFFu, v, off);
    int lane = threadIdx.x & 31;
    int wid  = threadIdx.x >> 5;
    if (lane == 0) shmem[wid] = v;
    __syncthreads();
    if (wid == 0) {
        float s = (lane < (BLOCK_N >> 5)) ? shmem[lane] : 0.0f;
        #pragma unroll
        for (int off = 16; off > 0; off >>= 1)
            s += __shfl_down_sync(0xFFFFFFFFu, s, off);
        return s;
    }
    return 0.0f;
}

__global__ void __launch_bounds__(BLOCK_N)
main_kernel(const float* __restrict__ pred_params,
            const float* __restrict__ step_preds,
            const float* __restrict__ cov,
            const float* __restrict__ theta,
            const int*   __restrict__ lengths,
            float*       __restrict__ out) {
    __shared__ float shmem[32];
    __shared__ int cur_b;

    float block_step, block_drift, block_gdiff;

    // ---- Phase 1: step-ahead term via dynamic batch queue ----
    // Block pops batch b; 16 groups of 16 lanes stride its live rows.
    // Uniform loop bounds, no per-row division, no dead iterations,
    // unconditional loads -> front-batched (high MLP).
    {
        const int g    = threadIdx.x >> 4;
        const int lane = threadIdx.x & 15;

        float local = 0.0f;
        for (;;) {
            if (threadIdx.x == 0)
                cur_b = (int)atomicAdd(&g_batch_ctr, 1u);
            __syncthreads();
            const int b = cur_b;
            __syncthreads();   // protect cur_b before next pop overwrites it
            if (b >= B_SZ) break;

            const int nrow = lengths[b] - 1;      // live rows: t in [0, nrow)
            if (nrow <= 0) continue;

            const float* __restrict__ pbase =
                step_preds + (size_t)b * TM1 * D_SZ + (lane << 2);
            const float* __restrict__ cbase =
                cov + (size_t)b * T_SZ * COV_ROW + COV_ROW + 1 + (lane << 2);

            float bacc = 0.0f;
            int t = g;
            for (; t + 16 < nrow; t += 32) {
                const float4 p0 = __ldcs(reinterpret_cast<const float4*>(
                    pbase + (size_t)t * D_SZ));
                const float4 p1 = __ldcs(reinterpret_cast<const float4*>(
                    pbase + (size_t)(t + 16) * D_SZ));
                const float* c0 = cbase + (size_t)t * COV_ROW;
                const float* c1 = cbase + (size_t)(t + 16) * COV_ROW;
                float a0 = __ldcs(c0 + 0) - p0.x;
                float a1 = __ldcs(c0 + 1) - p0.y;
                float a2 = __ldcs(c0 + 2) - p0.z;
                float a3 = __ldcs(c0 + 3) - p0.w;
                float b0 = __ldcs(c1 + 0) - p1.x;
                float b1 = __ldcs(c1 + 1) - p1.y;
                float b2 = __ldcs(c1 + 2) - p1.z;
                float b3 = __ldcs(c1 + 3) - p1.w;
                bacc += a0*a0 + a1*a1 + a2*a2 + a3*a3
                      + b0*b0 + b1*b1 + b2*b2 + b3*b3;
            }
            if (t < nrow) {
                const float4 p0 = __ldcs(reinterpret_cast<const float4*>(
                    pbase + (size_t)t * D_SZ));
                const float* c0 = cbase + (size_t)t * COV_ROW;
                float a0 = __ldcs(c0 + 0) - p0.x;
                float a1 = __ldcs(c0 + 1) - p0.y;
                float a2 = __ldcs(c0 + 2) - p0.z;
                float a3 = __ldcs(c0 + 3) - p0.w;
                bacc += a0*a0 + a1*a1 + a2*a2 + a3*a3;
            }
            local += bacc * (1.0f / ((float)nrow * (float)D_SZ));
        }

        block_step = block_reduce(local, shmem);
        __syncthreads();  // shmem reuse
    }

    // ---- Phase 2: drift + global-diff over pred_params [B,T,2] ----
    {
        const float inv_th0 = 1.0f / theta[0];
        const float inv_th1 = 1.0f / theta[1];
        const int n = B_SZ * T_SZ;   // 819200 float2 elements
        const int stride = GRID_N * BLOCK_N;

        float drift = 0.0f;
        float gdiff = 0.0f;
        for (int i = blockIdx.x * BLOCK_N + threadIdx.x; i < n; i += stride) {
            int t = i % T_SZ;
            float2 x = reinterpret_cast<const float2*>(pred_params)[i];
            float e0 = x.x * inv_th0 - 1.0f;
            float e1 = x.y * inv_th1 - 1.0f;
            gdiff += e0 * e0 + e1 * e1;
            if (t < T_SZ - 1) {
                float2 y = reinterpret_cast<const float2*>(pred_params)[i + 1];
                float d0 = x.x - y.x;
                float d1 = x.y - y.y;
                drift += d0 * d0 + d1 * d1;
            }
        }
        block_drift = block_reduce(drift, shmem);
        __syncthreads();
        block_gdiff = block_reduce(gdiff, shmem);
    }

    // ---- Phase 3: thread-0-only commit + ticket; last block finalizes ----
    __shared__ bool is_last;
    if (threadIdx.x == 0) {
        atomicAdd(&g_acc[0], (double)block_step);
        atomicAdd(&g_acc[1], (double)block_drift);
        atomicAdd(&g_acc[2], (double)block_gdiff);
        __threadfence();
        unsigned int t = atomicInc(&g_ticket, GRID_N - 1);  // wraps to 0
        is_last = (t == GRID_N - 1);
    }
    __syncthreads();
    if (!is_last) return;

    if (threadIdx.x == 0) {
        __threadfence();
        double step  = g_acc[0] / (double)B_SZ;
        double drift = g_acc[1] / ((double)B_SZ * (double)TM1 * (double)P_SZ);
        double gdiff = g_acc[2] / ((double)B_SZ * (double)T_SZ * (double)P_SZ);
        out[0] = (float)(step + 0.1 * drift + 0.01 * gdiff);
        // Reset state for the next graph replay.
        g_acc[0] = 0.0; g_acc[1] = 0.0; g_acc[2] = 0.0;
        g_batch_ctr = 0;
        __threadfence();
    }
}

extern "C" void kernel_launch(void* const* d_in, const int* in_sizes, int n_in,
                              void* d_out, int out_size) {
    const float* global_theta = (const float*)d_in[0];
    const float* pred_params  = (const float*)d_in[1];
    // d_in[2] = hidden_states: UNUSED by the reference
    const float* step_preds   = (const float*)d_in[3];
    const float* cov_trajs    = (const float*)d_in[4];
    const int*   lengths      = (const int*)d_in[5];
    float* out = (float*)d_out;

    main_kernel<<<GRID_N, BLOCK_N>>>(pred_params, step_preds, cov_trajs,
                                     global_theta, lengths, out);
}

// round 10
// speedup vs baseline: 1.2917x; 1.0402x over previous
#include <cuda_runtime.h>

// Problem constants
#define B_SZ 4096
#define T_SZ 200
#define D_SZ 64
#define P_SZ 2
#define TM1 (T_SZ - 1)     // 199
#define COV_ROW (D_SZ + 1) // 65

// Exactly one wave: 148 SMs x 8 blocks/SM (256 thr, 32 regs -> 2048 thr/SM)
#define GRID_N 1184
#define BLOCK_N 256

// Global accumulators + work queue. Static-init to 0; the finalizing block
// resets everything for the next graph replay.
__device__ double g_acc[3] = {0.0, 0.0, 0.0};
__device__ unsigned int g_ticket = 0;
__device__ unsigned int g_batch_ctr = 0;

// Reduce one float across the block; result valid on thread 0.
__device__ __forceinline__ float block_reduce(float v, float* shmem) {
    #pragma unroll
    for (int off = 16; off > 0; off >>= 1)
        v += __shfl_down_sync(0xFFFFFFFFu, v, off);
    int lane = threadIdx.x & 31;
    int wid  = threadIdx.x >> 5;
    if (lane == 0) shmem[wid] = v;
    __syncthreads();
    if (wid == 0) {
        float s = (lane < (BLOCK_N >> 5)) ? shmem[lane] : 0.0f;
        #pragma unroll
        for (int off = 16; off > 0; off >>= 1)
            s += __shfl_down_sync(0xFFFFFFFFu, s, off);
        return s;
    }
    return 0.0f;
}

__global__ void __launch_bounds__(BLOCK_N)
main_kernel(const float* __restrict__ pred_params,
            const float* __restrict__ step_preds,
            const float* __restrict__ cov,
            const float* __restrict__ theta,
            const int*   __restrict__ lengths,
            float*       __restrict__ out) {
    __shared__ float shmem[32];
    __shared__ int cur_b;

    float block_step, block_drift, block_gdiff;

    // ---- Phase 1: step-ahead term via dynamic batch queue ----
    {
        const int g    = threadIdx.x >> 4;
        const int lane = threadIdx.x & 15;

        float local = 0.0f;
        for (;;) {
            if (threadIdx.x == 0)
                cur_b = (int)atomicAdd(&g_batch_ctr, 1u);
            __syncthreads();
            const int b = cur_b;
            __syncthreads();   // protect cur_b before next pop overwrites it
            if (b >= B_SZ) break;

            const int nrow = lengths[b] - 1;      // live rows: t in [0, nrow)
            if (nrow <= 0) continue;

            const float* __restrict__ pbase =
                step_preds + (size_t)b * TM1 * D_SZ + (lane << 2);
            const float* __restrict__ cbase =
                cov + (size_t)b * T_SZ * COV_ROW + COV_ROW + 1 + (lane << 2);

            float bacc = 0.0f;
            int t = g;
            for (; t + 16 < nrow; t += 32) {
                const float4 p0 = __ldcs(reinterpret_cast<const float4*>(
                    pbase + (size_t)t * D_SZ));
                const float4 p1 = __ldcs(reinterpret_cast<const float4*>(
                    pbase + (size_t)(t + 16) * D_SZ));
                const float* c0 = cbase + (size_t)t * COV_ROW;
                const float* c1 = cbase + (size_t)(t + 16) * COV_ROW;
                float a0 = __ldcs(c0 + 0) - p0.x;
                float a1 = __ldcs(c0 + 1) - p0.y;
                float a2 = __ldcs(c0 + 2) - p0.z;
                float a3 = __ldcs(c0 + 3) - p0.w;
                float b0 = __ldcs(c1 + 0) - p1.x;
                float b1 = __ldcs(c1 + 1) - p1.y;
                float b2 = __ldcs(c1 + 2) - p1.z;
                float b3 = __ldcs(c1 + 3) - p1.w;
                bacc += a0*a0 + a1*a1 + a2*a2 + a3*a3
                      + b0*b0 + b1*b1 + b2*b2 + b3*b3;
            }
            if (t < nrow) {
                const float4 p0 = __ldcs(reinterpret_cast<const float4*>(
                    pbase + (size_t)t * D_SZ));
                const float* c0 = cbase + (size_t)t * COV_ROW;
                float a0 = __ldcs(c0 + 0) - p0.x;
                float a1 = __ldcs(c0 + 1) - p0.y;
                float a2 = __ldcs(c0 + 2) - p0.z;
                float a3 = __ldcs(c0 + 3) - p0.w;
                bacc += a0*a0 + a1*a1 + a2*a2 + a3*a3;
            }
            local += bacc * (1.0f / ((float)nrow * (float)D_SZ));
        }

        block_step = block_reduce(local, shmem);
        __syncthreads();  // shmem reuse
    }

    // ---- Phase 2: drift + global-diff over pred_params [B,T,2] ----
    {
        const float inv_th0 = 1.0f / theta[0];
        const float inv_th1 = 1.0f / theta[1];
        const int n = B_SZ * T_SZ;   // 819200 float2 elements
        const int stride = GRID_N * BLOCK_N;

        float drift = 0.0f;
        float gdiff = 0.0f;
        for (int i = blockIdx.x * BLOCK_N + threadIdx.x; i < n; i += stride) {
            int t = i % T_SZ;
            float2 x = reinterpret_cast<const float2*>(pred_params)[i];
            float e0 = x.x * inv_th0 - 1.0f;
            float e1 = x.y * inv_th1 - 1.0f;
            gdiff += e0 * e0 + e1 * e1;
            if (t < T_SZ - 1) {
                float2 y = reinterpret_cast<const float2*>(pred_params)[i + 1];
                float d0 = x.x - y.x;
                float d1 = x.y - y.y;
                drift += d0 * d0 + d1 * d1;
            }
        }
        block_drift = block_reduce(drift, shmem);
        __syncthreads();
        block_gdiff = block_reduce(gdiff, shmem);
    }

    // ---- Phase 3: thread-0-only commit + ticket; last block finalizes ----
    __shared__ bool is_last;
    if (threadIdx.x == 0) {
        atomicAdd(&g_acc[0], (double)block_step);
        atomicAdd(&g_acc[1], (double)block_drift);
        atomicAdd(&g_acc[2], (double)block_gdiff);
        __threadfence();
        unsigned int t = atomicInc(&g_ticket, GRID_N - 1);  // wraps to 0
        is_last = (t == GRID_N - 1);
    }
    __syncthreads();
    if (!is_last) return;

    if (threadIdx.x == 0) {
        __threadfence();
        double step  = g_acc[0] / (double)B_SZ;
        double drift = g_acc[1] / ((double)B_SZ * (double)TM1 * (double)P_SZ);
        double gdiff = g_acc[2] / ((double)B_SZ * (double)T_SZ * (double)P_SZ);
        out[0] = (float)(step + 0.1 * drift + 0.01 * gdiff);
        // Reset state for the next graph replay.
        g_acc[0] = 0.0; g_acc[1] = 0.0; g_acc[2] = 0.0;
        g_batch_ctr = 0;
        __threadfence();
    }
}

extern "C" void kernel_launch(void* const* d_in, const int* in_sizes, int n_in,
                              void* d_out, int out_size) {
    const float* global_theta = (const float*)d_in[0];
    const float* pred_params  = (const float*)d_in[1];
    // d_in[2] = hidden_states: UNUSED by the reference
    const float* step_preds   = (const float*)d_in[3];
    const float* cov_trajs    = (const float*)d_in[4];
    const int*   lengths      = (const int*)d_in[5];
    float* out = (float*)d_out;

    main_kernel<<<GRID_N, BLOCK_N>>>(pred_params, step_preds, cov_trajs,
                                     global_theta, lengths, out);
}

// round 11
// speedup vs baseline: 1.3157x; 1.0186x over previous
#include <cuda_runtime.h>

// Problem constants
#define B_SZ 4096
#define T_SZ 200
#define D_SZ 64
#define P_SZ 2
#define TM1 (T_SZ - 1)     // 199
#define COV_ROW (D_SZ + 1) // 65

// One wave: 148 SMs x 8 blocks/SM
#define GRID_N 1184
#define BLOCK_N 256
#define NWARP (BLOCK_N / 32)   // 8 warps
#define NQUANTA (2 * B_SZ)     // half-batch work quanta

// Global accumulators + work queue. Static-init to 0; the finalizing block
// resets everything for the next graph replay.
__device__ double g_acc[3] = {0.0, 0.0, 0.0};
__device__ unsigned int g_ticket = 0;
__device__ unsigned int g_batch_ctr = 0;

// Reduce one float across the block; result valid on thread 0.
__device__ __forceinline__ float block_reduce(float v, float* shmem) {
    #pragma unroll
    for (int off = 16; off > 0; off >>= 1)
        v += __shfl_down_sync(0xFFFFFFFFu, v, off);
    int lane = threadIdx.x & 31;
    int wid  = threadIdx.x >> 5;
    if (lane == 0) shmem[wid] = v;
    __syncthreads();
    if (wid == 0) {
        float s = (lane < NWARP) ? shmem[lane] : 0.0f;
        #pragma unroll
        for (int off = 16; off > 0; off >>= 1)
            s += __shfl_down_sync(0xFFFFFFFFu, s, off);
        return s;
    }
    return 0.0f;
}

__global__ void __launch_bounds__(BLOCK_N)
main_kernel(const float* __restrict__ pred_params,
            const float* __restrict__ step_preds,
            const float* __restrict__ cov,
            const float* __restrict__ theta,
            const int*   __restrict__ lengths,
            float*       __restrict__ out) {
    __shared__ float shmem[32];
    __shared__ int cur_q;

    float block_step, block_drift, block_gdiff;

    // ---- Phase 1: step-ahead term; warp-per-row, half-batch queue ----
    // Warp w of half h covers rows t = h*8 + w, stride 16.
    // Lane owns elements d = 2*lane, 2*lane+1:
    //   pred: aligned float2 (LDG.64, 2 wavefronts per 256B row)
    //   cov:  2 scalar loads (misaligned-by-4 stream)
    {
        const int w    = threadIdx.x >> 5;
        const int lane = threadIdx.x & 31;

        float local = 0.0f;
        for (;;) {
            if (threadIdx.x == 0)
                cur_q = (int)atomicAdd(&g_batch_ctr, 1u);
            __syncthreads();
            const int q = cur_q;
            __syncthreads();   // protect cur_q before next pop overwrites it
            if (q >= NQUANTA) break;

            const int b    = q >> 1;
            const int half = q & 1;
            const int nrow = lengths[b] - 1;      // live rows: t in [0, nrow)
            if (nrow <= 0) continue;

            const float* __restrict__ pbase =
                step_preds + (size_t)b * TM1 * D_SZ + (lane << 1);
            const float* __restrict__ cbase =
                cov + (size_t)b * T_SZ * COV_ROW + COV_ROW + 1 + (lane << 1);

            float bacc = 0.0f;
            int t = half * 8 + w;      // residues 0..15 over both halves
            // 2 rows in flight per iteration: t and t+16
            for (; t + 16 < nrow; t += 32) {
                const float2 p0 = __ldcs(reinterpret_cast<const float2*>(
                    pbase + (size_t)t * D_SZ));
                const float2 p1 = __ldcs(reinterpret_cast<const float2*>(
                    pbase + (size_t)(t + 16) * D_SZ));
                const float* c0 = cbase + (size_t)t * COV_ROW;
                const float* c1 = cbase + (size_t)(t + 16) * COV_ROW;
                float a0 = __ldcs(c0 + 0) - p0.x;
                float a1 = __ldcs(c0 + 1) - p0.y;
                float b0 = __ldcs(c1 + 0) - p1.x;
                float b1 = __ldcs(c1 + 1) - p1.y;
                bacc += a0*a0 + a1*a1 + b0*b0 + b1*b1;
            }
            if (t < nrow) {
                const float2 p0 = __ldcs(reinterpret_cast<const float2*>(
                    pbase + (size_t)t * D_SZ));
                const float* c0 = cbase + (size_t)t * COV_ROW;
                float a0 = __ldcs(c0 + 0) - p0.x;
                float a1 = __ldcs(c0 + 1) - p0.y;
                bacc += a0*a0 + a1*a1;
            }
            local += bacc * (1.0f / ((float)nrow * (float)D_SZ));
        }

        block_step = block_reduce(local, shmem);
        __syncthreads();  // shmem reuse
    }

    // ---- Phase 2: drift + global-diff over pred_params [B,T,2] ----
    {
        const float inv_th0 = 1.0f / theta[0];
        const float inv_th1 = 1.0f / theta[1];
        const int n = B_SZ * T_SZ;   // 819200 float2 elements
        const int stride = GRID_N * BLOCK_N;

        float drift = 0.0f;
        float gdiff = 0.0f;
        for (int i = blockIdx.x * BLOCK_N + threadIdx.x; i < n; i += stride) {
            int t = i % T_SZ;
            float2 x = reinterpret_cast<const float2*>(pred_params)[i];
            float e0 = x.x * inv_th0 - 1.0f;
            float e1 = x.y * inv_th1 - 1.0f;
            gdiff += e0 * e0 + e1 * e1;
            if (t < T_SZ - 1) {
                float2 y = reinterpret_cast<const float2*>(pred_params)[i + 1];
                float d0 = x.x - y.x;
                float d1 = x.y - y.y;
                drift += d0 * d0 + d1 * d1;
            }
        }
        block_drift = block_reduce(drift, shmem);
        __syncthreads();
        block_gdiff = block_reduce(gdiff, shmem);
    }

    // ---- Phase 3: thread-0-only commit + ticket; last block finalizes ----
    __shared__ bool is_last;
    if (threadIdx.x == 0) {
        atomicAdd(&g_acc[0], (double)block_step);
        atomicAdd(&g_acc[1], (double)block_drift);
        atomicAdd(&g_acc[2], (double)block_gdiff);
        __threadfence();
        unsigned int t = atomicInc(&g_ticket, GRID_N - 1);  // wraps to 0
        is_last = (t == GRID_N - 1);
    }
    __syncthreads();
    if (!is_last) return;

    if (threadIdx.x == 0) {
        __threadfence();
        double step  = g_acc[0] / (double)B_SZ;
        double drift = g_acc[1] / ((double)B_SZ * (double)TM1 * (double)P_SZ);
        double gdiff = g_acc[2] / ((double)B_SZ * (double)T_SZ * (double)P_SZ);
        out[0] = (float)(step + 0.1 * drift + 0.01 * gdiff);
        // Reset state for the next graph replay.
        g_acc[0] = 0.0; g_acc[1] = 0.0; g_acc[2] = 0.0;
        g_batch_ctr = 0;
        __threadfence();
    }
}

extern "C" void kernel_launch(void* const* d_in, const int* in_sizes, int n_in,
                              void* d_out, int out_size) {
    const float* global_theta = (const float*)d_in[0];
    const float* pred_params  = (const float*)d_in[1];
    // d_in[2] = hidden_states: UNUSED by the reference
    const float* step_preds   = (const float*)d_in[3];
    const float* cov_trajs    = (const float*)d_in[4];
    const int*   lengths      = (const int*)d_in[5];
    float* out = (float*)d_out;

    main_kernel<<<GRID_N, BLOCK_N>>>(pred_params, step_preds, cov_trajs,
                                     global_theta, lengths, out);
}

// round 15
// speedup vs baseline: 1.3624x; 1.0355x over previous
#include <cuda_runtime.h>

// Problem constants
#define B_SZ 4096
#define T_SZ 200
#define D_SZ 64
#define P_SZ 2
#define TM1 (T_SZ - 1)     // 199
#define COV_ROW (D_SZ + 1) // 65

// One wave at 6 blocks/SM: 148 x 6
#define BLOCKS_PER_SM 6
#define GRID_N (148 * BLOCKS_PER_SM)   // 888
#define BLOCK_N 256
#define NWARP (BLOCK_N / 32)           // 8 warps

// Global accumulators + work queue. Static-init to 0; the finalizing block
// resets everything for the next graph replay.
__device__ double g_acc[3] = {0.0, 0.0, 0.0};
__device__ unsigned int g_ticket = 0;
__device__ unsigned int g_batch_ctr = 0;

// Reduce one float across the block; result valid on thread 0.
__device__ __forceinline__ float block_reduce(float v, float* shmem) {
    #pragma unroll
    for (int off = 16; off > 0; off >>= 1)
        v += __shfl_down_sync(0xFFFFFFFFu, v, off);
    int lane = threadIdx.x & 31;
    int wid  = threadIdx.x >> 5;
    if (lane == 0) shmem[wid] = v;
    __syncthreads();
    if (wid == 0) {
        float s = (lane < NWARP) ? shmem[lane] : 0.0f;
        #pragma unroll
        for (int off = 16; off > 0; off >>= 1)
            s += __shfl_down_sync(0xFFFFFFFFu, s, off);
        return s;
    }
    return 0.0f;
}

__global__ void __launch_bounds__(BLOCK_N, BLOCKS_PER_SM)
main_kernel(const float* __restrict__ pred_params,
            const float* __restrict__ step_preds,
            const float* __restrict__ cov,
            const float* __restrict__ theta,
            const int*   __restrict__ lengths,
            float*       __restrict__ out) {
    __shared__ float shmem[32];
    __shared__ int cur_b;

    float block_step, block_drift, block_gdiff;

    // ---- Phase 1: step-ahead term; warp-per-row, 4 rows in flight ----
    {
        const int w    = threadIdx.x >> 5;
        const int lane = threadIdx.x & 31;

        float local = 0.0f;
        for (;;) {
            if (threadIdx.x == 0)
                cur_b = (int)atomicAdd(&g_batch_ctr, 1u);
            __syncthreads();
            const int b = cur_b;
            __syncthreads();   // protect cur_b before next pop overwrites it
            if (b >= B_SZ) break;

            const int nrow = lengths[b] - 1;      // live rows: t in [0, nrow)
            if (nrow <= 0) continue;

            const float* __restrict__ p0 =
                step_preds + (size_t)b * TM1 * D_SZ + (size_t)w * D_SZ + (lane << 1);
            const float* __restrict__ c0 =
                cov + (size_t)b * T_SZ * COV_ROW + (size_t)(w + 1) * COV_ROW + 1 + (lane << 1);

            // Strides for one warp-row step (8 rows of the batch)
            const int PSTEP = 8 * D_SZ;       // 512 floats
            const int CSTEP = 8 * COV_ROW;    // 520 floats

            float bacc = 0.0f;
            int t = w;
            for (; t + 24 < nrow; t += 32) {
                const float2 pa = __ldcs(reinterpret_cast<const float2*>(p0));
                const float2 pb = __ldcs(reinterpret_cast<const float2*>(p0 + PSTEP));
                const float2 pc = __ldcs(reinterpret_cast<const float2*>(p0 + 2 * PSTEP));
                const float2 pd = __ldcs(reinterpret_cast<const float2*>(p0 + 3 * PSTEP));
                float a0 = __ldcs(c0 + 0)             - pa.x;
                float a1 = __ldcs(c0 + 1)             - pa.y;
                float b0 = __ldcs(c0 + CSTEP + 0)     - pb.x;
                float b1 = __ldcs(c0 + CSTEP + 1)     - pb.y;
                float e0 = __ldcs(c0 + 2 * CSTEP + 0) - pc.x;
                float e1 = __ldcs(c0 + 2 * CSTEP + 1) - pc.y;
                float f0 = __ldcs(c0 + 3 * CSTEP + 0) - pd.x;
                float f1 = __ldcs(c0 + 3 * CSTEP + 1) - pd.y;
                bacc += a0*a0 + a1*a1 + b0*b0 + b1*b1
                      + e0*e0 + e1*e1 + f0*f0 + f1*f1;
                p0 += 4 * PSTEP;
                c0 += 4 * CSTEP;
            }
            // Remainder: up to 3 more rows for this warp
            for (; t < nrow; t += 8) {
                const float2 pa = __ldcs(reinterpret_cast<const float2*>(p0));
                float a0 = __ldcs(c0 + 0) - pa.x;
                float a1 = __ldcs(c0 + 1) - pa.y;
                bacc += a0*a0 + a1*a1;
                p0 += PSTEP;
                c0 += CSTEP;
            }
            local += bacc * (1.0f / ((float)nrow * (float)D_SZ));
        }

        block_step = block_reduce(local, shmem);
        __syncthreads();  // shmem reuse
    }

    // ---- Phase 2: drift + global-diff over pred_params [B,T,2] ----
    {
        const float inv_th0 = 1.0f / theta[0];
        const float inv_th1 = 1.0f / theta[1];
        const int n = B_SZ * T_SZ;   // 819200 float2 elements
        const int stride = GRID_N * BLOCK_N;

        float drift = 0.0f;
        float gdiff = 0.0f;
        for (int i = blockIdx.x * BLOCK_N + threadIdx.x; i < n; i += stride) {
            int t = i % T_SZ;
            float2 x = reinterpret_cast<const float2*>(pred_params)[i];
            float e0 = x.x * inv_th0 - 1.0f;
            float e1 = x.y * inv_th1 - 1.0f;
            gdiff += e0 * e0 + e1 * e1;
            if (t < T_SZ - 1) {
                float2 y = reinterpret_cast<const float2*>(pred_params)[i + 1];
                float d0 = x.x - y.x;
                float d1 = x.y - y.y;
                drift += d0 * d0 + d1 * d1;
            }
        }
        block_drift = block_reduce(drift, shmem);
        __syncthreads();
        block_gdiff = block_reduce(gdiff, shmem);
    }

    // ---- Phase 3: thread-0-only commit + ticket; last block finalizes ----
    __shared__ bool is_last;
    if (threadIdx.x == 0) {
        atomicAdd(&g_acc[0], (double)block_step);
        atomicAdd(&g_acc[1], (double)block_drift);
        atomicAdd(&g_acc[2], (double)block_gdiff);
        __threadfence();
        unsigned int t = atomicInc(&g_ticket, GRID_N - 1);  // wraps to 0
        is_last = (t == GRID_N - 1);
    }
    __syncthreads();
    if (!is_last) return;

    if (threadIdx.x == 0) {
        __threadfence();
        double step  = g_acc[0] / (double)B_SZ;
        double drift = g_acc[1] / ((double)B_SZ * (double)TM1 * (double)P_SZ);
        double gdiff = g_acc[2] / ((double)B_SZ * (double)T_SZ * (double)P_SZ);
        out[0] = (float)(step + 0.1 * drift + 0.01 * gdiff);
        // Reset state for the next graph replay.
        g_acc[0] = 0.0; g_acc[1] = 0.0; g_acc[2] = 0.0;
        g_batch_ctr = 0;
        __threadfence();
    }
}

extern "C" void kernel_launch(void* const* d_in, const int* in_sizes, int n_in,
                              void* d_out, int out_size) {
    const float* global_theta = (const float*)d_in[0];
    const float* pred_params  = (const float*)d_in[1];
    // d_in[2] = hidden_states: UNUSED by the reference
    const float* step_preds   = (const float*)d_in[3];
    const float* cov_trajs    = (const float*)d_in[4];
    const int*   lengths      = (const int*)d_in[5];
    float* out = (float*)d_out;

    main_kernel<<<GRID_N, BLOCK_N>>>(pred_params, step_preds, cov_trajs,
                                     global_theta, lengths, out);
}